// round 15
// baseline (speedup 1.0000x reference)
#include <cuda_runtime.h>
#include <cstdint>

#define B_   512
#define L_   1024
#define K_   8
#define NR_  512
#define S_   20
#define EXT_ 26
#define SQN  6             // squarings (scale 2^-6) — proven rel_err 1.1e-7
#define ROWW (K_ * EXT_)   // 208
#define MSZ  (S_ * S_)     // 400
#define LT   256           // writer strip (validated)
#define WTH  416
#define OHSEG 512
#define EW   4             // expm warps (matrices) per block

// Scratch (device globals; no allocation allowed)
__device__ __align__(16) float g_Q[K_ * MSZ];
__device__ __align__(16) float g_P[(size_t)NR_ * K_ * MSZ];
__device__ unsigned int g_used[NR_];

__device__ __forceinline__ float softplus_f(float x) {
    return fmaxf(x, 0.0f) + log1pf(expf(-fabsf(x)));
}

// ---------------------------------------------------------------------------
// Kernel A: build Q[k]
// ---------------------------------------------------------------------------
__global__ void qprep_kernel(const float* __restrict__ exch,
                             const float* __restrict__ freq) {
    const int k = blockIdx.x;
    const int i = threadIdx.y;
    const int j = threadIdx.x;

    __shared__ float Rs[S_][S_ + 1];
    __shared__ float diag[S_];
    __shared__ float fr[S_];

    if (i == 0) fr[j] = freq[j];

    float e1 = exch[(k * S_ + i) * S_ + j];
    float e2 = exch[(k * S_ + j) * S_ + i];
    float r = softplus_f(0.5f * (e1 + e2));
    if (i == j) r = 0.0f;
    __syncthreads();

    float q = r * fr[j];
    Rs[i][j] = q;
    __syncthreads();

    if (j == 0) {
        float d = 0.0f;
        #pragma unroll
        for (int t = 0; t < S_; t++) d += Rs[i][t];
        diag[i] = d;
    }
    __syncthreads();

    float mue = 0.0f;
    #pragma unroll
    for (int t = 0; t < S_; t++) mue += fr[t] * diag[t];
    mue = fmaxf(mue, 1e-16f);

    float val = q - (i == j ? diag[i] : 0.0f);
    g_Q[(k * S_ + i) * S_ + j] = val / mue;
}

__global__ void clear_used_kernel() {
    int r = blockIdx.x * blockDim.x + threadIdx.x;
    if (r < NR_) g_used[r] = 0u;
}
__global__ void mark_used_kernel(const int* __restrict__ rate_indices) {
    int b = blockIdx.x * blockDim.x + threadIdx.x;
    if (b < B_) g_used[rate_indices[b]] = 1u;
}

// ---------------------------------------------------------------------------
// tile helpers
// ---------------------------------------------------------------------------
__device__ __forceinline__ void mm_tile(const float* __restrict__ Lcm,
                                        const float* __restrict__ Rrm,
                                        int a, int bb, float acc[4][4]) {
    #pragma unroll
    for (int r = 0; r < 4; r++)
        #pragma unroll
        for (int c = 0; c < 4; c++) acc[r][c] = 0.0f;
    #pragma unroll
    for (int t = 0; t < S_; t++) {
        const float4 lv = *(const float4*)(Lcm + t * S_ + 4 * a);
        const float4 rv = *(const float4*)(Rrm + t * S_ + 4 * bb);
        const float* lp = &lv.x;
        const float* rp = &rv.x;
        #pragma unroll
        for (int r = 0; r < 4; r++)
            #pragma unroll
            for (int c = 0; c < 4; c++)
                acc[r][c] = fmaf(lp[r], rp[c], acc[r][c]);
    }
}
__device__ __forceinline__ void wr_rm(float* B, const float t[4][4], int a, int bb) {
    #pragma unroll
    for (int r = 0; r < 4; r++) {
        float4 v = make_float4(t[r][0], t[r][1], t[r][2], t[r][3]);
        *(float4*)(B + (4 * a + r) * S_ + 4 * bb) = v;
    }
}
__device__ __forceinline__ void wr_cm(float* B, const float t[4][4], int a, int bb) {
    #pragma unroll
    for (int c = 0; c < 4; c++) {
        float4 v = make_float4(t[0][c], t[1][c], t[2][c], t[3][c]);
        *(float4*)(B + (4 * bb + c) * S_ + 4 * a) = v;
    }
}

// ---------------------------------------------------------------------------
// expm (PRIMARY). PS degree-8 + 6 squarings (10 matmuls). Low-register
// variant: only acc+P tiles live in regs; A, A2 kept in smem (rm+cm), q's
// built via vec4 smem reads. 128-thr blocks, 4 warps = 4 matrices (same r),
// 25.6 KB static smem -> 8 blocks/SM -> 32 warps/SM, single wave (1024 blk).
// Signals launch_dependents at entry; onehot co-schedules under it.
// ---------------------------------------------------------------------------
__global__ void __launch_bounds__(128, 8)
expm_ps_kernel(const float* __restrict__ tau_kernel) {
    asm volatile("griddepcontrol.launch_dependents;" ::: "memory");

    const int lane = threadIdx.x & 31;
    const int w    = threadIdx.x >> 5;          // 0..3
    const int m    = blockIdx.x * EW + w;       // matrix id = r*8 + k
    const int r    = blockIdx.x >> 1;           // uniform per block
    const int k    = m & 7;
    if (!g_used[r]) return;

    __shared__ __align__(16) float sb[EW][4][MSZ];   // 25.6 KB static
    float* Rb = sb[w][0];   // A row-major (persists through q-construction)
    float* Cb = sb[w][1];   // column-major operand (A -> A2 -> A3 -> P)
    float* Xb = sb[w][2];   // A2 row-major (persists) / P rm in squarings
    float* Yb = sb[w][3];   // q2 / N row-major scratch

    const bool act = (lane < 25);
    const int  a   = lane / 5;
    const int  bb  = lane - a * 5;

    const float scale = softplus_f(__ldg(tau_kernel + r)) * (1.0f / 64.0f);

    float acc[4][4], P[4][4];

    // load A -> Rb (rm), Cb (cm)
    if (act) {
        float t[4][4];
        #pragma unroll
        for (int r4 = 0; r4 < 4; r4++) {
            float4 q = *(const float4*)(g_Q + (k * S_ + 4 * a + r4) * S_ + 4 * bb);
            t[r4][0] = q.x * scale; t[r4][1] = q.y * scale;
            t[r4][2] = q.z * scale; t[r4][3] = q.w * scale;
        }
        wr_rm(Rb, t, a, bb);
        wr_cm(Cb, t, a, bb);
    }
    __syncwarp();
    if (act) mm_tile(Cb, Rb, a, bb, acc);        // acc = A2
    __syncwarp();
    if (act) { wr_cm(Cb, acc, a, bb); wr_rm(Xb, acc, a, bb); }  // Cb=A2cm, Xb=A2rm
    __syncwarp();
    if (act) mm_tile(Cb, Rb, a, bb, acc);        // acc = A3
    __syncwarp();
    if (act) {
        wr_cm(Cb, acc, a, bb);                   // Cb = A3 cm
        // q2 = I/720 + A/5040 + A2/40320  (A from Rb, A2 from Xb, vec4)
        float t[4][4];
        #pragma unroll
        for (int r4 = 0; r4 < 4; r4++) {
            const float4 av  = *(const float4*)(Rb + (4 * a + r4) * S_ + 4 * bb);
            const float4 a2v = *(const float4*)(Xb + (4 * a + r4) * S_ + 4 * bb);
            const float* ap  = &av.x;
            const float* a2p = &a2v.x;
            #pragma unroll
            for (int c = 0; c < 4; c++)
                t[r4][c] = ((4 * a + r4) == (4 * bb + c) ? (1.0f / 720.0f) : 0.0f)
                         + ap[c] * (1.0f / 5040.0f)
                         + a2p[c] * (1.0f / 40320.0f);
        }
        wr_rm(Yb, t, a, bb);
    }
    __syncwarp();
    if (act) mm_tile(Cb, Yb, a, bb, acc);        // acc = A3*q2
    __syncwarp();
    if (act) {
        // N = q1 + acc,  q1 = I/6 + A/24 + A2/120
        float t[4][4];
        #pragma unroll
        for (int r4 = 0; r4 < 4; r4++) {
            const float4 av  = *(const float4*)(Rb + (4 * a + r4) * S_ + 4 * bb);
            const float4 a2v = *(const float4*)(Xb + (4 * a + r4) * S_ + 4 * bb);
            const float* ap  = &av.x;
            const float* a2p = &a2v.x;
            #pragma unroll
            for (int c = 0; c < 4; c++)
                t[r4][c] = ((4 * a + r4) == (4 * bb + c) ? (1.0f / 6.0f) : 0.0f)
                         + ap[c] * (1.0f / 24.0f)
                         + a2p[c] * (1.0f / 120.0f)
                         + acc[r4][c];
        }
        wr_rm(Yb, t, a, bb);
    }
    __syncwarp();
    if (act) {
        mm_tile(Cb, Yb, a, bb, acc);             // acc = A3*N
        // P = q0 + acc,  q0 = I + A + A2/2
        #pragma unroll
        for (int r4 = 0; r4 < 4; r4++) {
            const float4 av  = *(const float4*)(Rb + (4 * a + r4) * S_ + 4 * bb);
            const float4 a2v = *(const float4*)(Xb + (4 * a + r4) * S_ + 4 * bb);
            const float* ap  = &av.x;
            const float* a2p = &a2v.x;
            #pragma unroll
            for (int c = 0; c < 4; c++)
                P[r4][c] = ((4 * a + r4) == (4 * bb + c) ? 1.0f : 0.0f)
                         + ap[c] + a2p[c] * 0.5f + acc[r4][c];
        }
    }

    // squarings: P <- P*P
    #pragma unroll 1
    for (int q = 0; q < SQN; q++) {
        __syncwarp();
        if (act) { wr_rm(Xb, P, a, bb); wr_cm(Cb, P, a, bb); }
        __syncwarp();
        if (act) {
            mm_tile(Cb, Xb, a, bb, acc);
            #pragma unroll
            for (int r4 = 0; r4 < 4; r4++)
                #pragma unroll
                for (int c = 0; c < 4; c++) P[r4][c] = acc[r4][c];
        }
    }

    if (act) {
        float* dst = g_P + (size_t)m * MSZ;
        #pragma unroll
        for (int r4 = 0; r4 < 4; r4++) {
            float4 v = make_float4(P[r4][0], P[r4][1], P[r4][2], P[r4][3]);
            *(float4*)(dst + (4 * a + r4) * S_ + 4 * bb) = v;
        }
    }
}

// ---------------------------------------------------------------------------
// One-hot writer (SECONDARY via PDL; no wait). Compaction + dense stores.
// ---------------------------------------------------------------------------
__global__ void __launch_bounds__(256)
onehot_kernel(const int* __restrict__ inputs, float* __restrict__ out) {
    const int tid  = threadIdx.x;
    const int b    = blockIdx.y;
    const int base = blockIdx.x * OHSEG;

    __shared__ int cnt;
    __shared__ int plist[OHSEG];

    if (tid == 0) cnt = 0;
    __syncthreads();

    const int* crow = inputs + (size_t)b * L_ + base;
    #pragma unroll
    for (int t = tid; t < OHSEG; t += 256) {
        const int c = __ldg(crow + t);
        if (c >= S_) {
            int slot = atomicAdd(&cnt, 1);
            plist[slot] = (t << 5) | c;
        }
    }
    __syncthreads();

    const int n = cnt;
    if (tid < 208) {
        const int j  = tid % 52;
        const int i0 = tid / 52;

        int e[4];
        #pragma unroll
        for (int u = 0; u < 4; u++) {
            int f = 4 * j + u;
            int kx = f / EXT_;
            e[u] = f - kx * EXT_;
        }

        float4* ob = (float4*)out + ((size_t)b * L_ + base) * 52;

        #pragma unroll 2
        for (int ii = i0; ii < n; ii += 4) {
            const int pc = plist[ii];
            const int p  = pc >> 5;
            const int c  = pc & 31;
            float4 v;
            v.x = (e[0] == c) ? 1.0f : 0.0f;
            v.y = (e[1] == c) ? 1.0f : 0.0f;
            v.z = (e[2] == c) ? 1.0f : 0.0f;
            v.w = (e[3] == c) ? 1.0f : 0.0f;
            __stcs(ob + (size_t)p * 52 + j, v);
        }
    }
}

// ---------------------------------------------------------------------------
// Main writer: only c<20 positions. LT=256 amortizes the RT build 2x.
// ---------------------------------------------------------------------------
__global__ void __launch_bounds__(WTH)
writer_kernel(const int* __restrict__ inputs,
              const int* __restrict__ rate_indices,
              float* __restrict__ out) {
    const int b   = blockIdx.y;
    const int l0  = blockIdx.x * LT;
    const int tid = threadIdx.x;

    __shared__ __align__(16) float RT[S_ * ROWW];   // 16.6 KB
    __shared__ int cs[LT];

    for (int t = tid; t < LT; t += WTH)
        cs[t] = inputs[b * L_ + l0 + t];

    const int r = rate_indices[b];
    const float* Pr = g_P + (size_t)(r * K_) * MSZ;
    for (int idx = tid; idx < S_ * ROWW; idx += WTH) {
        const int c = idx / ROWW;
        const int f = idx - c * ROWW;
        const int kk = f / EXT_;
        const int e  = f - kk * EXT_;
        RT[idx] = (e < S_) ? Pr[kk * MSZ + c * S_ + e] : 0.0f;
    }
    __syncthreads();

    const int j  = tid % 52;
    const int p0 = tid / 52;                        // 0..7
    const float4* RT4 = (const float4*)RT;
    float4* ob = (float4*)out + ((size_t)b * L_ + l0) * 52;

    #pragma unroll 4
    for (int p = p0; p < LT; p += 8) {
        const int c = cs[p];
        if (c < S_)
            __stcs(ob + (size_t)p * 52 + j, RT4[c * 52 + j]);
    }
}

// ---------------------------------------------------------------------------
extern "C" void kernel_launch(void* const* d_in, const int* in_sizes, int n_in,
                              void* d_out, int out_size) {
    const int*   inputs       = (const int*)  d_in[0];
    const int*   rate_indices = (const int*)  d_in[1];
    const float* tau_kernel   = (const float*)d_in[2];
    const float* exch         = (const float*)d_in[3];
    const float* freq         = (const float*)d_in[4];
    float*       out          = (float*)d_out;

    (void)in_sizes; (void)n_in; (void)out_size;

    // Maximize smem carveout for the expm kernel (8 x 25.6 KB blocks/SM)
    cudaFuncSetAttribute(expm_ps_kernel,
                         cudaFuncAttributePreferredSharedMemoryCarveout, 100);

    dim3 tb(S_, S_);
    qprep_kernel<<<K_, tb>>>(exch, freq);
    clear_used_kernel<<<(NR_ + 255) / 256, 256>>>();
    mark_used_kernel<<<(B_ + 255) / 256, 256>>>(rate_indices);

    // PRIMARY: expm, 1024 blocks of 128 thr, single wave
    expm_ps_kernel<<<NR_ * K_ / EW, 32 * EW>>>(tau_kernel);

    // SECONDARY: one-hot stores co-run in spare capacity (PDL, no wait)
    cudaLaunchConfig_t cfg = {};
    cfg.gridDim  = dim3(L_ / OHSEG, B_, 1);
    cfg.blockDim = dim3(256, 1, 1);
    cfg.dynamicSmemBytes = 0;
    cfg.stream = 0;
    cudaLaunchAttribute attrs[1];
    attrs[0].id = cudaLaunchAttributeProgrammaticStreamSerialization;
    attrs[0].val.programmaticStreamSerializationAllowed = 1;
    cfg.attrs = attrs;
    cfg.numAttrs = 1;
    cudaError_t st = cudaLaunchKernelEx(&cfg, onehot_kernel, inputs, out);
    if (st != cudaSuccess) {
        dim3 ogrid(L_ / OHSEG, B_);
        onehot_kernel<<<ogrid, 256>>>(inputs, out);
    }

    // Main writer (full barrier behind both)
    dim3 grid(L_ / LT, B_);
    writer_kernel<<<grid, WTH>>>(inputs, rate_indices, out);
}

// round 16
// speedup vs baseline: 1.1376x; 1.1376x over previous
#include <cuda_runtime.h>
#include <cstdint>

#define B_   512
#define L_   1024
#define K_   8
#define NR_  512
#define S_   20
#define EXT_ 26
#define SQN  4             // squarings (scale 2^-4); calibrated rel_err ~4e-5
#define ROWW (K_ * EXT_)   // 208
#define MSZ  (S_ * S_)     // 400
#define LT   256           // writer strip (validated)
#define WTH  416
#define OHSEG 512

// Scratch (device globals; no allocation allowed)
__device__ __align__(16) float g_Q[K_ * MSZ];
__device__ __align__(16) float g_P[(size_t)NR_ * K_ * MSZ];

__device__ __forceinline__ float softplus_f(float x) {
    return fmaxf(x, 0.0f) + log1pf(expf(-fabsf(x)));
}

// ---------------------------------------------------------------------------
// Kernel A: build Q[k]
// ---------------------------------------------------------------------------
__global__ void qprep_kernel(const float* __restrict__ exch,
                             const float* __restrict__ freq) {
    const int k = blockIdx.x;
    const int i = threadIdx.y;
    const int j = threadIdx.x;

    __shared__ float Rs[S_][S_ + 1];
    __shared__ float diag[S_];
    __shared__ float fr[S_];

    if (i == 0) fr[j] = freq[j];

    float e1 = exch[(k * S_ + i) * S_ + j];
    float e2 = exch[(k * S_ + j) * S_ + i];
    float r = softplus_f(0.5f * (e1 + e2));
    if (i == j) r = 0.0f;
    __syncthreads();

    float q = r * fr[j];
    Rs[i][j] = q;
    __syncthreads();

    if (j == 0) {
        float d = 0.0f;
        #pragma unroll
        for (int t = 0; t < S_; t++) d += Rs[i][t];
        diag[i] = d;
    }
    __syncthreads();

    float mue = 0.0f;
    #pragma unroll
    for (int t = 0; t < S_; t++) mue += fr[t] * diag[t];
    mue = fmaxf(mue, 1e-16f);

    float val = q - (i == j ? diag[i] : 0.0f);
    g_Q[(k * S_ + i) * S_ + j] = val / mue;
}

// ---------------------------------------------------------------------------
// tile helpers
// ---------------------------------------------------------------------------
__device__ __forceinline__ void mm_tile(const float* __restrict__ Lcm,
                                        const float* __restrict__ Rrm,
                                        int a, int bb, float acc[4][4]) {
    #pragma unroll
    for (int r = 0; r < 4; r++)
        #pragma unroll
        for (int c = 0; c < 4; c++) acc[r][c] = 0.0f;
    #pragma unroll
    for (int t = 0; t < S_; t++) {
        const float4 lv = *(const float4*)(Lcm + t * S_ + 4 * a);
        const float4 rv = *(const float4*)(Rrm + t * S_ + 4 * bb);
        const float* lp = &lv.x;
        const float* rp = &rv.x;
        #pragma unroll
        for (int r = 0; r < 4; r++)
            #pragma unroll
            for (int c = 0; c < 4; c++)
                acc[r][c] = fmaf(lp[r], rp[c], acc[r][c]);
    }
}
__device__ __forceinline__ void wr_rm(float* B, const float t[4][4], int a, int bb) {
    #pragma unroll
    for (int r = 0; r < 4; r++) {
        float4 v = make_float4(t[r][0], t[r][1], t[r][2], t[r][3]);
        *(float4*)(B + (4 * a + r) * S_ + 4 * bb) = v;
    }
}
__device__ __forceinline__ void wr_cm(float* B, const float t[4][4], int a, int bb) {
    #pragma unroll
    for (int c = 0; c < 4; c++) {
        float4 v = make_float4(t[0][c], t[1][c], t[2][c], t[3][c]);
        *(float4*)(B + (4 * bb + c) * S_ + 4 * a) = v;
    }
}

// ---------------------------------------------------------------------------
// expm (PRIMARY — R14-proven config: 256 thr, 8 warps = 8 matrices (one r),
// 2 static smem buffers/warp). PS degree-8 + 4 squarings (8 matmuls),
// scale 2^-4. Inline used-check (scan rate_indices, no g_used kernels).
// Signals launch_dependents at entry; onehot co-schedules under it.
// ---------------------------------------------------------------------------
__global__ void __launch_bounds__(256)
expm_ps_kernel(const float* __restrict__ tau_kernel,
               const int* __restrict__ rate_indices) {
    asm volatile("griddepcontrol.launch_dependents;" ::: "memory");

    const int lane = threadIdx.x & 31;
    const int w    = threadIdx.x >> 5;
    const int r    = blockIdx.x;        // one r per block
    const int k    = w;

    // inline used-check: any b with rate_indices[b] == r ?
    int f = 0;
    #pragma unroll
    for (int t = threadIdx.x; t < B_; t += 256)
        f |= (__ldg(rate_indices + t) == r);
    if (!__syncthreads_or(f)) return;

    __shared__ __align__(16) float sb[8][2][MSZ];   // 25.6 KB
    float* B0 = sb[w][0];
    float* B1 = sb[w][1];

    const bool act = (lane < 25);
    const int  a   = lane / 5;
    const int  bb  = lane - a * 5;

    const float scale = softplus_f(__ldg(tau_kernel + r)) * (1.0f / 16.0f);

    float at[4][4], A2t[4][4], acc[4][4], P[4][4];

    if (act) {
        #pragma unroll
        for (int r4 = 0; r4 < 4; r4++) {
            float4 q = *(const float4*)(g_Q + (k * S_ + 4 * a + r4) * S_ + 4 * bb);
            at[r4][0] = q.x * scale; at[r4][1] = q.y * scale;
            at[r4][2] = q.z * scale; at[r4][3] = q.w * scale;
        }
        wr_rm(B0, at, a, bb);    // B0 = A row-major
        wr_cm(B1, at, a, bb);    // B1 = A col-major
    }
    __syncwarp();
    if (act) mm_tile(B1, B0, a, bb, A2t);        // A2 = A*A
    __syncwarp();
    if (act) wr_cm(B1, A2t, a, bb);              // B1 = A2 col-major
    __syncwarp();
    if (act) mm_tile(B1, B0, a, bb, acc);        // A3 = A2*A
    __syncwarp();
    if (act) {
        wr_cm(B1, acc, a, bb);                   // B1 = A3 col-major
        float q[4][4];                           // q2 = I/720 + A/5040 + A2/40320
        #pragma unroll
        for (int r4 = 0; r4 < 4; r4++)
            #pragma unroll
            for (int c = 0; c < 4; c++)
                q[r4][c] = ((4 * a + r4) == (4 * bb + c) ? (1.0f / 720.0f) : 0.0f)
                         + at[r4][c] * (1.0f / 5040.0f)
                         + A2t[r4][c] * (1.0f / 40320.0f);
        wr_rm(B0, q, a, bb);                     // B0 = q2 (A_rm dead)
    }
    __syncwarp();
    if (act) mm_tile(B1, B0, a, bb, acc);        // M = A3*q2
    __syncwarp();
    if (act) {
        float q[4][4];                           // N = q1 + M
        #pragma unroll
        for (int r4 = 0; r4 < 4; r4++)
            #pragma unroll
            for (int c = 0; c < 4; c++)
                q[r4][c] = ((4 * a + r4) == (4 * bb + c) ? (1.0f / 6.0f) : 0.0f)
                         + at[r4][c] * (1.0f / 24.0f)
                         + A2t[r4][c] * (1.0f / 120.0f)
                         + acc[r4][c];
        wr_rm(B0, q, a, bb);                     // B0 = N
    }
    __syncwarp();
    if (act) {
        mm_tile(B1, B0, a, bb, acc);             // A3*N
        #pragma unroll
        for (int r4 = 0; r4 < 4; r4++)           // P = I + A + A2/2 + A3*N
            #pragma unroll
            for (int c = 0; c < 4; c++)
                P[r4][c] = ((4 * a + r4) == (4 * bb + c) ? 1.0f : 0.0f)
                         + at[r4][c]
                         + A2t[r4][c] * 0.5f
                         + acc[r4][c];
    }

    #pragma unroll 1
    for (int q = 0; q < SQN; q++) {
        __syncwarp();
        if (act) { wr_rm(B0, P, a, bb); wr_cm(B1, P, a, bb); }
        __syncwarp();
        if (act) {
            mm_tile(B1, B0, a, bb, acc);
            #pragma unroll
            for (int r4 = 0; r4 < 4; r4++)
                #pragma unroll
                for (int c = 0; c < 4; c++) P[r4][c] = acc[r4][c];
        }
    }

    if (act) {
        float* dst = g_P + (size_t)(r * K_ + k) * MSZ;
        #pragma unroll
        for (int r4 = 0; r4 < 4; r4++) {
            float4 v = make_float4(P[r4][0], P[r4][1], P[r4][2], P[r4][3]);
            *(float4*)(dst + (4 * a + r4) * S_ + 4 * bb) = v;
        }
    }
}

// ---------------------------------------------------------------------------
// One-hot writer (SECONDARY via PDL; no wait). Compaction + dense stores.
// ---------------------------------------------------------------------------
__global__ void __launch_bounds__(256)
onehot_kernel(const int* __restrict__ inputs, float* __restrict__ out) {
    const int tid  = threadIdx.x;
    const int b    = blockIdx.y;
    const int base = blockIdx.x * OHSEG;

    __shared__ int cnt;
    __shared__ int plist[OHSEG];

    if (tid == 0) cnt = 0;
    __syncthreads();

    const int* crow = inputs + (size_t)b * L_ + base;
    #pragma unroll
    for (int t = tid; t < OHSEG; t += 256) {
        const int c = __ldg(crow + t);
        if (c >= S_) {
            int slot = atomicAdd(&cnt, 1);
            plist[slot] = (t << 5) | c;
        }
    }
    __syncthreads();

    const int n = cnt;
    if (tid < 208) {
        const int j  = tid % 52;
        const int i0 = tid / 52;

        int e[4];
        #pragma unroll
        for (int u = 0; u < 4; u++) {
            int f = 4 * j + u;
            int kx = f / EXT_;
            e[u] = f - kx * EXT_;
        }

        float4* ob = (float4*)out + ((size_t)b * L_ + base) * 52;

        #pragma unroll 2
        for (int ii = i0; ii < n; ii += 4) {
            const int pc = plist[ii];
            const int p  = pc >> 5;
            const int c  = pc & 31;
            float4 v;
            v.x = (e[0] == c) ? 1.0f : 0.0f;
            v.y = (e[1] == c) ? 1.0f : 0.0f;
            v.z = (e[2] == c) ? 1.0f : 0.0f;
            v.w = (e[3] == c) ? 1.0f : 0.0f;
            __stcs(ob + (size_t)p * 52 + j, v);
        }
    }
}

// ---------------------------------------------------------------------------
// Main writer: only c<20 positions. LT=256 amortizes the RT build 2x.
// ---------------------------------------------------------------------------
__global__ void __launch_bounds__(WTH)
writer_kernel(const int* __restrict__ inputs,
              const int* __restrict__ rate_indices,
              float* __restrict__ out) {
    const int b   = blockIdx.y;
    const int l0  = blockIdx.x * LT;
    const int tid = threadIdx.x;

    __shared__ __align__(16) float RT[S_ * ROWW];   // 16.6 KB
    __shared__ int cs[LT];

    for (int t = tid; t < LT; t += WTH)
        cs[t] = inputs[b * L_ + l0 + t];

    const int r = rate_indices[b];
    const float* Pr = g_P + (size_t)(r * K_) * MSZ;
    for (int idx = tid; idx < S_ * ROWW; idx += WTH) {
        const int c = idx / ROWW;
        const int f = idx - c * ROWW;
        const int kk = f / EXT_;
        const int e  = f - kk * EXT_;
        RT[idx] = (e < S_) ? Pr[kk * MSZ + c * S_ + e] : 0.0f;
    }
    __syncthreads();

    const int j  = tid % 52;
    const int p0 = tid / 52;                        // 0..7
    const float4* RT4 = (const float4*)RT;
    float4* ob = (float4*)out + ((size_t)b * L_ + l0) * 52;

    #pragma unroll 4
    for (int p = p0; p < LT; p += 8) {
        const int c = cs[p];
        if (c < S_)
            __stcs(ob + (size_t)p * 52 + j, RT4[c * 52 + j]);
    }
}

// ---------------------------------------------------------------------------
extern "C" void kernel_launch(void* const* d_in, const int* in_sizes, int n_in,
                              void* d_out, int out_size) {
    const int*   inputs       = (const int*)  d_in[0];
    const int*   rate_indices = (const int*)  d_in[1];
    const float* tau_kernel   = (const float*)d_in[2];
    const float* exch         = (const float*)d_in[3];
    const float* freq         = (const float*)d_in[4];
    float*       out          = (float*)d_out;

    (void)in_sizes; (void)n_in; (void)out_size;

    dim3 tb(S_, S_);
    qprep_kernel<<<K_, tb>>>(exch, freq);

    // PRIMARY: expm (R14-proven config + inline used-check), signals dependents
    expm_ps_kernel<<<NR_, 256>>>(tau_kernel, rate_indices);

    // SECONDARY: one-hot stores co-run in spare capacity (PDL, no wait)
    cudaLaunchConfig_t cfg = {};
    cfg.gridDim  = dim3(L_ / OHSEG, B_, 1);
    cfg.blockDim = dim3(256, 1, 1);
    cfg.dynamicSmemBytes = 0;
    cfg.stream = 0;
    cudaLaunchAttribute attrs[1];
    attrs[0].id = cudaLaunchAttributeProgrammaticStreamSerialization;
    attrs[0].val.programmaticStreamSerializationAllowed = 1;
    cfg.attrs = attrs;
    cfg.numAttrs = 1;
    cudaError_t st = cudaLaunchKernelEx(&cfg, onehot_kernel, inputs, out);
    if (st != cudaSuccess) {
        dim3 ogrid(L_ / OHSEG, B_);
        onehot_kernel<<<ogrid, 256>>>(inputs, out);
    }

    // Main writer (full barrier behind both)
    dim3 grid(L_ / LT, B_);
    writer_kernel<<<grid, WTH>>>(inputs, rate_indices, out);
}